// round 15
// baseline (speedup 1.0000x reference)
#include <cuda_runtime.h>

#define GRID 148
#define TPB  1024

__device__ unsigned g_counter = 0;          // monotone ticket counter (replay-safe)
__device__ float g_partials[GRID * 16];     // [block][8 sums, 8 sumsq]

__device__ __forceinline__ float ex2f(float x) {
    float y; asm("ex2.approx.ftz.f32 %0, %1;" : "=f"(y) : "f"(x)); return y;
}
__device__ __forceinline__ float sin_fast(float x) {
    float y; asm("sin.approx.ftz.f32 %0, %1;" : "=f"(y) : "f"(x)); return y;
}

__global__ __launch_bounds__(TPB, 1)
void qfnn_kernel(const float* __restrict__ xg, float* __restrict__ outg,
                 const float* __restrict__ W1g, const float* __restrict__ b1g,
                 const float* __restrict__ gamg, const float* __restrict__ betg,
                 const float* __restrict__ mg, const float* __restrict__ thg,
                 const float* __restrict__ g2g, const float* __restrict__ bt2g,
                 const float* __restrict__ W2g, const float* __restrict__ b2g,
                 int n, int rpb)
{
    // static smem: parameters (distinct objects from dynamic cache -> hoistable)
    __shared__ float w1s[30];    // W1
    __shared__ float w2s[24];    // W2 rows 0..2 (original)
    __shared__ float w2p[24];    // W2 pre-scaled by sc (filled after grid barrier)
    __shared__ float sprm[15];   // b1 0..2, m' 3..8, c2' 9..14
    __shared__ float scs[8], t2s[8], bps[3];
    __shared__ float red[512];
    // dynamic smem: 6-plane membership cache
    extern __shared__ float ps[];

    const int bid = blockIdx.x, tid = threadIdx.x;

    // ---- prologue ----
    if      (tid < 30) w1s[tid] = W1g[tid];
    else if (tid < 54) w2s[tid - 30] = W2g[tid - 30];
    else if (tid < 57) sprm[tid - 54] = b1g[tid - 54];
    else if (tid < 63) {               // m'[k] = (m[k]-bet[q])/gam[q]
        const int k = tid - 57, q = k >> 1;
        sprm[3 + k] = (mg[k] - betg[q]) / gamg[q];
    } else if (tid < 69) {             // c2'[k] = -log2e/(2 th^2)*gam[q]^2
        const int k = tid - 63, q = k >> 1;
        const float g = gamg[q], t = thg[k];
        sprm[9 + k] = (-1.4426950408889634f / (2.0f * t * t)) * g * g;
    }
    __syncthreads();

    const int row0 = bid * rpb;
    int nrows = n - row0;
    if (nrows > rpb) nrows = rpb;
    if (nrows < 0) nrows = 0;

    float accS[8], accQ[8];
#pragma unroll
    for (int c = 0; c < 8; c++) { accS[c] = 0.f; accQ[c] = 0.f; }

    const float C2 = 0.99999f * 0.99999f;

    // ---------------- Pass 1 (barrier-free): x -> memberships (cached) + sums ----------------
    for (int r = tid; r < nrows; r += TPB) {
        const float2* xp = (const float2*)(xg + (size_t)(row0 + r) * 10);
        float h0 = sprm[0], h1 = sprm[1], h2 = sprm[2];
#pragma unroll
        for (int j = 0; j < 5; j++) {
            const float2 v = xp[j];
            h0 = fmaf(v.x, w1s[0 + 2 * j],      h0);
            h0 = fmaf(v.y, w1s[0 + 2 * j + 1],  h0);
            h1 = fmaf(v.x, w1s[10 + 2 * j],     h1);
            h1 = fmaf(v.y, w1s[10 + 2 * j + 1], h1);
            h2 = fmaf(v.x, w1s[20 + 2 * j],     h2);
            h2 = fmaf(v.y, w1s[20 + 2 * j + 1], h2);
        }
        const float mu = (h0 + h1 + h2) * (1.0f / 3.0f);
        const float d0 = h0 - mu, d1 = h1 - mu, d2 = h2 - mu;
        const float var = (d0 * d0 + d1 * d1 + d2 * d2) * (1.0f / 3.0f);
        const float rn = rsqrtf(var + 1e-5f);
        const float z0 = d0 * rn, z1 = d1 * rn, z2 = d2 * rn;

        float p[6];
#pragma unroll
        for (int kk = 0; kk < 6; kk++) {
            const float zq = (kk < 2) ? z0 : (kk < 4) ? z1 : z2;
            const float a = zq - sprm[3 + kk];
            const float f = ex2f(a * a * sprm[9 + kk]);
            const float pv = fminf(f + 1e-16f, C2);
            p[kk] = (kk < 2) ? pv : (1.0f - pv);
        }
        ps[0 * rpb + r] = p[0]; ps[1 * rpb + r] = p[1];
        ps[2 * rpb + r] = p[2]; ps[3 * rpb + r] = p[3];
        ps[4 * rpb + r] = p[4]; ps[5 * rpb + r] = p[5];

        const float w00 = p[2] * p[4], w01 = p[2] * p[5];
        const float w10 = p[3] * p[4], w11 = p[3] * p[5];
        float o[8];
        o[0] = p[0] * w00; o[1] = p[0] * w01; o[2] = p[0] * w10; o[3] = p[0] * w11;
        o[4] = p[1] * w00; o[5] = p[1] * w01; o[6] = p[1] * w10; o[7] = p[1] * w11;
#pragma unroll
        for (int c = 0; c < 8; c++) {
            accS[c] += o[c];
            accQ[c] = fmaf(o[c], o[c], accQ[c]);
        }
    }

    // ---------------- Block reduction (deterministic) ----------------
    {
        const int lane = tid & 31, wrp = tid >> 5;
#pragma unroll
        for (int k = 0; k < 16; k++) {
            float v = (k < 8) ? accS[k] : accQ[k - 8];
#pragma unroll
            for (int off = 16; off; off >>= 1)
                v += __shfl_down_sync(0xffffffffu, v, off);
            if (lane == 0) red[wrp * 16 + k] = v;
        }
    }
    __syncthreads();
    if (tid < 16) {
        float s = 0.f;
#pragma unroll
        for (int w = 0; w < TPB / 32; w++) s += red[w * 16 + tid];
        g_partials[bid * 16 + tid] = s;
        __threadfence();
    }
    __syncthreads();

    // ---------------- Grid barrier (ticketed, replay-safe) ----------------
    if (tid == 0) {
        __threadfence();
        const unsigned tk = atomicAdd(&g_counter, 1u);
        const unsigned target = (tk / GRID + 1u) * GRID;
        while (*((volatile unsigned*)&g_counter) < target) { }
    }
    __syncthreads();
    __threadfence();

    // ---------------- Finalize BN constants ----------------
    if (tid < 16) {
        float s0 = 0.f, s1 = 0.f, s2v = 0.f, s3 = 0.f;
#pragma unroll 4
        for (int b = 0; b < GRID; b += 4) {
            s0  += __ldcg(&g_partials[(b + 0) * 16 + tid]);
            s1  += __ldcg(&g_partials[(b + 1) * 16 + tid]);
            s2v += __ldcg(&g_partials[(b + 2) * 16 + tid]);
            s3  += __ldcg(&g_partials[(b + 3) * 16 + tid]);
        }
        red[tid] = (s0 + s1) + (s2v + s3);
    }
    __syncthreads();
    if (tid < 8) {
        const float invB = 1.0f / (float)n;
        const float muv = red[tid] * invB;
        const float msq = red[tid + 8] * invB;
        const float var = msq - muv * muv;
        const float sc = g2g[tid] * rsqrtf(var + 1e-5f);
        scs[tid] = sc;
        t2s[tid] = bt2g[tid] - muv * sc;
    }
    __syncthreads();
    if (tid < 24) {                   // pre-scale W2 by sc
        w2p[tid] = w2s[tid] * scs[tid & 7];
    } else if (tid < 27) {            // bp[i] = b2[i] + sum_c t2[c]*W2[i,c]
        const int i = tid - 24;
        float a = b2g[i];
#pragma unroll
        for (int c = 0; c < 8; c++) a = fmaf(t2s[c], w2s[i * 8 + c], a);
        bps[i] = a;
    }
    __syncthreads();

    // ---------------- Pass 2 (barrier-free): memberships -> logits -> result ----------------
    for (int r = tid; r < nrows; r += TPB) {
        const float p0 = ps[0 * rpb + r], p1 = ps[1 * rpb + r];
        const float p2 = ps[2 * rpb + r], p3 = ps[3 * rpb + r];
        const float p4 = ps[4 * rpb + r], p5 = ps[5 * rpb + r];
        const float w00 = p2 * p4, w01 = p2 * p5, w10 = p3 * p4, w11 = p3 * p5;
        float o[8];
        o[0] = p0 * w00; o[1] = p0 * w01; o[2] = p0 * w10; o[3] = p0 * w11;
        o[4] = p1 * w00; o[5] = p1 * w01; o[6] = p1 * w10; o[7] = p1 * w11;
        float lg[3];
#pragma unroll
        for (int i = 0; i < 3; i++) {
            float a = bps[i];
#pragma unroll
            for (int c = 0; c < 8; c++) a = fmaf(o[c], w2p[i * 8 + c], a);
            lg[i] = a;
        }
        const float sg0 = sin_fast(lg[0] * 0.5f);
        const float sg1 = sin_fast(lg[1] * 0.5f);
        const float sg2 = sin_fast(lg[2] * 0.5f);
        const float pq0 = sg0 * sg0, pq1 = sg1 * sg1, pq2 = sg2 * sg2;
        const float cq0 = 1.f - pq0, cq1 = 1.f - pq1, cq2 = 1.f - pq2;
        const float tt = cq1 * cq2;
        float* dst = outg + (size_t)(row0 + r) * 3;
        dst[0] = cq0 * tt;
        dst[1] = pq0 * tt;
        dst[2] = cq0 * (pq1 * cq2);
    }
}

extern "C" void kernel_launch(void* const* d_in, const int* in_sizes, int n_in,
                              void* d_out, int out_size)
{
    const float* x = (const float*)d_in[0];
    const int n = in_sizes[0] / 10;                 // 1048576
    const int rpb = (n + GRID - 1) / GRID;          // 7085

    const size_t smem = (size_t)(6 * rpb) * sizeof(float);
    cudaFuncSetAttribute(qfnn_kernel, cudaFuncAttributeMaxDynamicSharedMemorySize, (int)smem);
    qfnn_kernel<<<GRID, TPB, smem, 0>>>(
        x, (float*)d_out,
        (const float*)d_in[1], (const float*)d_in[2], (const float*)d_in[3],
        (const float*)d_in[4], (const float*)d_in[5], (const float*)d_in[6],
        (const float*)d_in[7], (const float*)d_in[8], (const float*)d_in[9],
        (const float*)d_in[10], n, rpb);
}

// round 16
// speedup vs baseline: 1.4031x; 1.4031x over previous
#include <cuda_runtime.h>

#define GRID 148
#define TPB  1024

__device__ unsigned g_counter = 0;          // monotone ticket counter (replay-safe)
__device__ float g_partials[GRID * 16];     // [block][8 sums, 8 sumsq]

__device__ __forceinline__ float ex2f(float x) {
    float y; asm("ex2.approx.ftz.f32 %0, %1;" : "=f"(y) : "f"(x)); return y;
}
__device__ __forceinline__ float sin_fast(float x) {
    float y; asm("sin.approx.ftz.f32 %0, %1;" : "=f"(y) : "f"(x)); return y;
}

// dynamic smem float offsets
#define OW1   0     // w1[30] (pad 32)
#define OW2P  32    // w2p[24] (pre-scaled, filled after barrier)
#define OB1   64    // b1[3]
#define OMP   67    // m'[6]
#define OC2   73    // c2'[6]
#define OBPS  80    // bps[3]
#define OSCS  84    // scs[8]
#define OT2   92    // t2[8]
#define ORED  128   // red[512]
#define OPS   640   // membership cache: 3 float2 planes, 2*rpb floats each

__global__ __launch_bounds__(TPB, 1)
void qfnn_kernel(const float* __restrict__ xg, float* __restrict__ outg,
                 const float* __restrict__ W1g, const float* __restrict__ b1g,
                 const float* __restrict__ gamg, const float* __restrict__ betg,
                 const float* __restrict__ mg, const float* __restrict__ thg,
                 const float* __restrict__ g2g, const float* __restrict__ bt2g,
                 const float* __restrict__ W2g, const float* __restrict__ b2g,
                 int n, int rpb)
{
    extern __shared__ float sm[];
    float* red = sm + ORED;
    float2* psA = (float2*)(sm + OPS);                 // (p0,p1)
    float2* psB = (float2*)(sm + OPS + 2 * rpb);       // (p2,p3)
    float2* psC = (float2*)(sm + OPS + 4 * rpb);       // (p4,p5)

    const int bid = blockIdx.x, tid = threadIdx.x;

    // ---- prologue: params -> smem (W1 raw; small params folded) ----
    if      (tid < 30) sm[OW1 + tid] = W1g[tid];
    else if (tid < 33) sm[OB1 + tid - 30] = b1g[tid - 30];
    else if (tid < 39) {            // m'[k] = (m[k]-bet[q])/gam[q]
        const int k = tid - 33, q = k >> 1;
        sm[OMP + k] = (mg[k] - betg[q]) / gamg[q];
    } else if (tid < 45) {          // c2'[k] = -log2e/(2 th^2) * gam[q]^2
        const int k = tid - 39, q = k >> 1;
        const float g = gamg[q], t = thg[k];
        sm[OC2 + k] = (-1.4426950408889634f / (2.0f * t * t)) * g * g;
    }
    __syncthreads();

    // small params -> registers (15 floats; cheap, no spill risk)
    float bb1[3], mvp[6], c2p[6];
#pragma unroll
    for (int i = 0; i < 3; i++) bb1[i] = sm[OB1 + i];
#pragma unroll
    for (int k = 0; k < 6; k++) { mvp[k] = sm[OMP + k]; c2p[k] = sm[OC2 + k]; }

    const int row0 = bid * rpb;
    int nrows = n - row0;
    if (nrows > rpb) nrows = rpb;
    if (nrows < 0) nrows = 0;

    float accS[8], accQ[8];
#pragma unroll
    for (int c = 0; c < 8; c++) { accS[c] = 0.f; accQ[c] = 0.f; }

    const float C2 = 0.99999f * 0.99999f;
    const float2* w1p = (const float2*)(sm + OW1);   // [q*5 + j]

    // ---------------- Pass 1 (barrier-free): x -> memberships (cached) + sums ----------------
    for (int r = tid; r < nrows; r += TPB) {
        const float2* xp = (const float2*)(xg + (size_t)(row0 + r) * 10);
        float h0 = bb1[0], h1 = bb1[1], h2 = bb1[2];
#pragma unroll
        for (int j = 0; j < 5; j++) {
            const float2 v = xp[j];
            const float2 a0 = w1p[j], a1 = w1p[5 + j], a2 = w1p[10 + j];
            h0 = fmaf(v.x, a0.x, h0); h0 = fmaf(v.y, a0.y, h0);
            h1 = fmaf(v.x, a1.x, h1); h1 = fmaf(v.y, a1.y, h1);
            h2 = fmaf(v.x, a2.x, h2); h2 = fmaf(v.y, a2.y, h2);
        }
        const float mu = (h0 + h1 + h2) * (1.0f / 3.0f);
        const float d0 = h0 - mu, d1 = h1 - mu, d2 = h2 - mu;
        const float var = (d0 * d0 + d1 * d1 + d2 * d2) * (1.0f / 3.0f);
        const float rn = rsqrtf(var + 1e-5f);
        const float z0 = d0 * rn, z1 = d1 * rn, z2 = d2 * rn;

        float p[6];
#pragma unroll
        for (int kk = 0; kk < 6; kk++) {
            const float zq = (kk < 2) ? z0 : (kk < 4) ? z1 : z2;
            const float a = zq - mvp[kk];
            const float f = ex2f(a * a * c2p[kk]);
            const float pv = fminf(f, C2);
            p[kk] = (kk < 2) ? pv : (1.0f - pv);
        }
        psA[r] = make_float2(p[0], p[1]);
        psB[r] = make_float2(p[2], p[3]);
        psC[r] = make_float2(p[4], p[5]);

        const float w00 = p[2] * p[4], w01 = p[2] * p[5];
        const float w10 = p[3] * p[4], w11 = p[3] * p[5];
        float o[8];
        o[0] = p[0] * w00; o[1] = p[0] * w01; o[2] = p[0] * w10; o[3] = p[0] * w11;
        o[4] = p[1] * w00; o[5] = p[1] * w01; o[6] = p[1] * w10; o[7] = p[1] * w11;
#pragma unroll
        for (int c = 0; c < 8; c++) {
            accS[c] += o[c];
            accQ[c] = fmaf(o[c], o[c], accQ[c]);
        }
    }

    // ---------------- Block reduction (deterministic) ----------------
    {
        const int lane = tid & 31, wrp = tid >> 5;
#pragma unroll
        for (int k = 0; k < 16; k++) {
            float v = (k < 8) ? accS[k] : accQ[k - 8];
#pragma unroll
            for (int off = 16; off; off >>= 1)
                v += __shfl_down_sync(0xffffffffu, v, off);
            if (lane == 0) red[wrp * 16 + k] = v;
        }
    }
    __syncthreads();
    if (tid < 16) {
        float s = 0.f;
#pragma unroll
        for (int w = 0; w < TPB / 32; w++) s += red[w * 16 + tid];
        g_partials[bid * 16 + tid] = s;
        __threadfence();
    }
    __syncthreads();

    // ---------------- Grid barrier (ticketed, replay-safe) ----------------
    if (tid == 0) {
        __threadfence();
        const unsigned tk = atomicAdd(&g_counter, 1u);
        const unsigned target = (tk / GRID + 1u) * GRID;
        while (*((volatile unsigned*)&g_counter) < target) { }
    }
    __syncthreads();
    __threadfence();

    // ---------------- Finalize BN constants ----------------
    if (tid < 16) {
        float s0 = 0.f, s1 = 0.f, s2v = 0.f, s3 = 0.f;
#pragma unroll 4
        for (int b = 0; b < GRID; b += 4) {
            s0  += __ldcg(&g_partials[(b + 0) * 16 + tid]);
            s1  += __ldcg(&g_partials[(b + 1) * 16 + tid]);
            s2v += __ldcg(&g_partials[(b + 2) * 16 + tid]);
            s3  += __ldcg(&g_partials[(b + 3) * 16 + tid]);
        }
        red[tid] = (s0 + s1) + (s2v + s3);
    }
    __syncthreads();
    if (tid < 8) {
        const float invB = 1.0f / (float)n;
        const float muv = red[tid] * invB;
        const float msq = red[tid + 8] * invB;
        const float var = msq - muv * muv;
        const float sc = g2g[tid] * rsqrtf(var + 1e-5f);
        sm[OSCS + tid] = sc;
        sm[OT2 + tid] = bt2g[tid] - muv * sc;
    }
    __syncthreads();
    if (tid < 24) {                  // w2p[i*8+c] = W2[i*8+c] * sc[c]  (W2 loaded here only)
        sm[OW2P + tid] = W2g[tid] * sm[OSCS + (tid & 7)];
    } else if (tid < 27) {           // bps[i] = b2[i] + sum_c t2[c]*W2[i*8+c]
        const int i = tid - 24;
        float a = b2g[i];
#pragma unroll
        for (int c = 0; c < 8; c++) a = fmaf(sm[OT2 + c], W2g[i * 8 + c], a);
        sm[OBPS + i] = a;
    }
    __syncthreads();

    const float bp0 = sm[OBPS + 0], bp1 = sm[OBPS + 1], bp2v = sm[OBPS + 2];
    const float2* w2q = (const float2*)(sm + OW2P);  // [i*4 + cp]

    // ---------------- Pass 2 (barrier-free): memberships -> logits -> result ----------------
    for (int r = tid; r < nrows; r += TPB) {
        const float2 A = psA[r], Bv = psB[r], Cv = psC[r];
        const float p0 = A.x, p1 = A.y, p2 = Bv.x, p3 = Bv.y, p4 = Cv.x, p5 = Cv.y;
        const float w00 = p2 * p4, w01 = p2 * p5, w10 = p3 * p4, w11 = p3 * p5;
        float o[8];
        o[0] = p0 * w00; o[1] = p0 * w01; o[2] = p0 * w10; o[3] = p0 * w11;
        o[4] = p1 * w00; o[5] = p1 * w01; o[6] = p1 * w10; o[7] = p1 * w11;
        float lg[3];
        const float bps[3] = {bp0, bp1, bp2v};
#pragma unroll
        for (int i = 0; i < 3; i++) {
            float a = bps[i];
#pragma unroll
            for (int cp = 0; cp < 4; cp++) {
                const float2 w = w2q[i * 4 + cp];
                a = fmaf(o[2 * cp], w.x, a);
                a = fmaf(o[2 * cp + 1], w.y, a);
            }
            lg[i] = a;
        }
        const float sg0 = sin_fast(lg[0] * 0.5f);
        const float sg1 = sin_fast(lg[1] * 0.5f);
        const float sg2 = sin_fast(lg[2] * 0.5f);
        const float pq0 = sg0 * sg0, pq1 = sg1 * sg1, pq2 = sg2 * sg2;
        const float cq0 = 1.f - pq0, cq1 = 1.f - pq1, cq2 = 1.f - pq2;
        const float tt = cq1 * cq2;
        float* dst = outg + (size_t)(row0 + r) * 3;
        dst[0] = cq0 * tt;
        dst[1] = pq0 * tt;
        dst[2] = cq0 * (pq1 * cq2);
    }
}

extern "C" void kernel_launch(void* const* d_in, const int* in_sizes, int n_in,
                              void* d_out, int out_size)
{
    const float* x = (const float*)d_in[0];
    const int n = in_sizes[0] / 10;                 // 1048576
    const int rpb = (n + GRID - 1) / GRID;          // 7085

    const size_t smem = (size_t)(OPS + 6 * rpb) * sizeof(float);
    cudaFuncSetAttribute(qfnn_kernel, cudaFuncAttributeMaxDynamicSharedMemorySize, (int)smem);
    qfnn_kernel<<<GRID, TPB, smem, 0>>>(
        x, (float*)d_out,
        (const float*)d_in[1], (const float*)d_in[2], (const float*)d_in[3],
        (const float*)d_in[4], (const float*)d_in[5], (const float*)d_in[6],
        (const float*)d_in[7], (const float*)d_in[8], (const float*)d_in[9],
        (const float*)d_in[10], n, rpb);
}